// round 3
// baseline (speedup 1.0000x reference)
#include <cuda_runtime.h>

// SBNet block-sparse 3x3 conv, fp32, packed f32x2 FMA path. R2: 448 threads
// (14 warps/SM) for latency hiding; 2 couts/thread; aligned LDS.64 weight pairs.
// Layouts: x[4][64][448][448], mask[4][1][448][448], weight[64][64][3][3],
// bias[64], out[4][64][448][448]. 14x14 output blocks; active iff
// max(mask over 16x16 window at offset -1) > 0.5.

namespace {
constexpr int Himg = 448, Wimg = 448, Cin = 64, Cout = 64;
constexpr int BS = 14;
constexpr int NBLK = 32 * 32;      // blocks per image
constexpr int TPB = 448;           // 14 rows x 32 cout-pairs
constexpr int WS_K_STRIDE = 66;    // even (aligned LDS.64) + bank-spread (66%32=2)
constexpr int WS_C_STRIDE = 9 * WS_K_STRIDE;   // 594
constexpr int XS_FLOATS = Cin * 256;           // 16384 (16x16 tile per c)
constexpr int WS_FLOATS = Cin * WS_C_STRIDE;   // 38016
constexpr int SMEM_BYTES = (XS_FLOATS + WS_FLOATS) * 4;  // 217600 B
}

__device__ __forceinline__ unsigned long long pk2(float lo, float hi) {
    unsigned long long r;
    asm("mov.b64 %0, {%1,%2};" : "=l"(r) : "f"(lo), "f"(hi));
    return r;
}
__device__ __forceinline__ void fma2(unsigned long long& d,
                                     unsigned long long a,
                                     unsigned long long b) {
    asm("fma.rn.f32x2 %0, %1, %2, %0;" : "+l"(d) : "l"(a), "l"(b));
}

__global__ __launch_bounds__(TPB, 1)
void sbnet_conv_kernel(const float* __restrict__ x,
                       const float* __restrict__ mask,
                       const float* __restrict__ weight,
                       const float* __restrict__ bias,
                       float* __restrict__ out) {
    extern __shared__ float smem[];
    float* xs = smem;                 // [c][16][16]
    float* ws = smem + XS_FLOATS;     // [c][k(stride 66)][o]

    const int b   = blockIdx.x;
    const int n   = b >> 10;
    const int rem = b & (NBLK - 1);
    const int by  = rem >> 5, bx = rem & 31;
    const int t   = threadIdx.x;
    const int y0  = by * BS, x0 = bx * BS;

    // ---- block activity: max of mask over 16x16 gather window ----
    float mv = 0.f;
    const float* mplane = mask + (size_t)n * Himg * Wimg;
    if (t < 256) {
        int ty = t >> 4, tx = t & 15;
        int gy = y0 - 1 + ty, gx = x0 - 1 + tx;
        if ((unsigned)gy < (unsigned)Himg && (unsigned)gx < (unsigned)Wimg)
            mv = mplane[gy * Wimg + gx];
    }
    const int act = __syncthreads_or(mv > 0.5f);

    const int r  = t >> 5;    // output row 0..13
    const int cg = t & 31;    // cout pair index (2 couts each)
    const int obase0 = ((n * Cout + cg * 2) * Himg + (y0 + r)) * Wimg + x0;

    if (!act) {  // inactive: write zeros (out buffer is poisoned)
        const float2 z = make_float2(0.f, 0.f);
        #pragma unroll
        for (int oi = 0; oi < 2; oi++) {
            float2* op = (float2*)(out + obase0 + oi * Himg * Wimg);
            #pragma unroll
            for (int j = 0; j < 7; j++) op[j] = z;
        }
        return;
    }

    // ---- stage input tile (with 1px halo, zero-padded) ----
    const float* xpl = x + (size_t)n * Cin * Himg * Wimg;
    for (int i = t; i < XS_FLOATS; i += TPB) {
        int c = i >> 8, p = i & 255;
        int ty = p >> 4, tx = p & 15;
        int gy = y0 - 1 + ty, gx = x0 - 1 + tx;
        float v = 0.f;
        if ((unsigned)gy < (unsigned)Himg && (unsigned)gx < (unsigned)Wimg)
            v = xpl[(c * Himg + gy) * Wimg + gx];
        xs[i] = v;
    }
    // ---- stage weights: global [o][c][k] (coalesced reads) -> smem [c][k][o]
    for (int i = t; i < Cout * Cin * 9; i += TPB) {
        int o  = i / 576;                  // global index order: o slow
        int r2 = i - o * 576;
        int c  = r2 / 9;
        int k  = r2 - c * 9;
        ws[c * WS_C_STRIDE + k * WS_K_STRIDE + o] = weight[i];
    }
    __syncthreads();

    // ---- compute: 14 px (7 f32x2 pairs) x 2 couts per thread ----
    unsigned long long acc[2][7];
    #pragma unroll
    for (int oi = 0; oi < 2; oi++)
        #pragma unroll
        for (int j = 0; j < 7; j++) acc[oi][j] = 0ULL;  // bits of (0.f,0.f)

    const float* wbase = ws + cg * 2;

    #pragma unroll 2
    for (int c = 0; c < Cin; c++) {
        const float* xr = xs + c * 256;
        const float* wr = wbase + c * WS_C_STRIDE;
        #pragma unroll
        for (int dy = 0; dy < 3; dy++) {
            const float4* rowp = (const float4*)(xr + (r + dy) * 16);
            float4 a0 = rowp[0], a1 = rowp[1], a2 = rowp[2], a3 = rowp[3];
            float v[16] = {a0.x, a0.y, a0.z, a0.w, a1.x, a1.y, a1.z, a1.w,
                           a2.x, a2.y, a2.z, a2.w, a3.x, a3.y, a3.z, a3.w};
            unsigned long long pe[8], po[7];
            #pragma unroll
            for (int j = 0; j < 8; j++) pe[j] = pk2(v[2 * j], v[2 * j + 1]);
            #pragma unroll
            for (int j = 0; j < 7; j++) po[j] = pk2(v[2 * j + 1], v[2 * j + 2]);

            // aligned float2 weight loads: both couts for each tap
            float2 wp0 = *(const float2*)(wr + (dy * 3 + 0) * WS_K_STRIDE);
            float2 wp1 = *(const float2*)(wr + (dy * 3 + 1) * WS_K_STRIDE);
            float2 wp2 = *(const float2*)(wr + (dy * 3 + 2) * WS_K_STRIDE);
            unsigned long long W[2][3] = {
                {pk2(wp0.x, wp0.x), pk2(wp1.x, wp1.x), pk2(wp2.x, wp2.x)},
                {pk2(wp0.y, wp0.y), pk2(wp1.y, wp1.y), pk2(wp2.y, wp2.y)}};
            #pragma unroll
            for (int oi = 0; oi < 2; oi++) {
                #pragma unroll
                for (int j = 0; j < 7; j++) {
                    fma2(acc[oi][j], pe[j],     W[oi][0]);
                    fma2(acc[oi][j], po[j],     W[oi][1]);
                    fma2(acc[oi][j], pe[j + 1], W[oi][2]);
                }
            }
        }
    }

    // ---- epilogue: add bias, store as float2 (x0 even -> aligned) ----
    #pragma unroll
    for (int oi = 0; oi < 2; oi++) {
        const float bo = __ldg(bias + cg * 2 + oi);
        float* op = out + obase0 + oi * Himg * Wimg;
        #pragma unroll
        for (int j = 0; j < 7; j++) {
            float2 f = *(float2*)&acc[oi][j];
            f.x += bo; f.y += bo;
            *(float2*)(op + 2 * j) = f;
        }
    }
}

extern "C" void kernel_launch(void* const* d_in, const int* in_sizes, int n_in,
                              void* d_out, int out_size) {
    const float* x      = (const float*)d_in[0];
    const float* mask   = (const float*)d_in[1];
    const float* weight = (const float*)d_in[2];
    const float* bias   = (const float*)d_in[3];
    float* out = (float*)d_out;

    cudaFuncSetAttribute(sbnet_conv_kernel,
                         cudaFuncAttributeMaxDynamicSharedMemorySize, SMEM_BYTES);
    sbnet_conv_kernel<<<4 * NBLK, TPB, SMEM_BYTES>>>(x, mask, weight, bias, out);
}

// round 5
// speedup vs baseline: 1.3544x; 1.3544x over previous
#include <cuda_runtime.h>
#include <cuda_bf16.h>
#include <cstdint>

// SBNet block-sparse 3x3 conv via mma.sync (HMMA) bf16-split implicit GEMM.
// x[4][64][448][448] f32, mask[4][1][448][448], weight[64][64][3][3], bias[64],
// out[4][64][448][448]. 14x14 output blocks; active iff max(mask over 16x16
// gather window at offset -1) > 0.5.
//
// Per active block: C[p][o] = sum_{tap,c} X[p + 16*ky + kx][c] * W[tap][o][c],
// p = y*16+x over the 16x16 gather tile; only (y<14 && x<14) stored.
// fp32 accuracy via bf16 split: out ~= xh*wh + xl*wh + xh*wl (3 passes).

namespace {
constexpr int Himg = 448, Wimg = 448, NBLK = 1024, TPB = 256;
constexpr int BS = 14;
constexpr int SM_X_HI = 1024;          // [0..256) bias
constexpr int XB = 256 * 128;          // 256 pixel-rows x 64ch bf16
constexpr int SM_X_LO = SM_X_HI + XB;  // 33792
constexpr int WB = 9 * 64 * 128;       // 9 taps x 64 cout rows x 64 cin bf16
constexpr int SM_W_HI = SM_X_LO + XB;  // 66560
constexpr int SM_W_LO = SM_W_HI + WB;  // 140288
constexpr int SMEM_TOTAL = SM_W_LO + WB;  // 214016
}

__device__ uint16_t g_whi[9 * 64 * 64];
__device__ uint16_t g_wlo[9 * 64 * 64];

__device__ __forceinline__ uint32_t smem_u32(const void* p) {
    uint32_t a;
    asm("{ .reg .u64 t; cvta.to.shared.u64 t, %1; cvt.u32.u64 %0, t; }"
        : "=r"(a) : "l"(p));
    return a;
}
__device__ __forceinline__ void ldsm4(uint32_t* r, uint32_t addr) {
    asm volatile("ldmatrix.sync.aligned.m8n8.x4.shared.b16 {%0,%1,%2,%3}, [%4];"
                 : "=r"(r[0]), "=r"(r[1]), "=r"(r[2]), "=r"(r[3]) : "r"(addr));
}
__device__ __forceinline__ void mma_bf16(float* d, const uint32_t* a,
                                         const uint32_t* b) {
    asm volatile(
        "mma.sync.aligned.m16n8k16.row.col.f32.bf16.bf16.f32 "
        "{%0,%1,%2,%3},{%4,%5,%6,%7},{%8,%9},{%0,%1,%2,%3};"
        : "+f"(d[0]), "+f"(d[1]), "+f"(d[2]), "+f"(d[3])
        : "r"(a[0]), "r"(a[1]), "r"(a[2]), "r"(a[3]), "r"(b[0]), "r"(b[1]));
}

// one-time: weight[o][c][ky][kx] f32 -> swizzled bf16 hi/lo, layout
// [tap][o-row(128B)][cin], 16B-chunk swizzle: chunk ^= (o&7).
__global__ void wconv_kernel(const float* __restrict__ w) {
    int i = blockIdx.x * blockDim.x + threadIdx.x;
    if (i >= 64 * 64 * 9) return;
    int o = i / 576, r = i - o * 576, c = r / 9, k = r - c * 9;
    float v = w[i];
    __nv_bfloat16 hi = __float2bfloat16(v);
    __nv_bfloat16 lo = __float2bfloat16(v - __bfloat162float(hi));
    uint32_t off16 = k * 4096 + o * 64 + ((((c >> 3) ^ (o & 7)) << 3)) + (c & 7);
    g_whi[off16] = __bfloat16_as_ushort(hi);
    g_wlo[off16] = __bfloat16_as_ushort(lo);
}

__global__ __launch_bounds__(TPB, 1)
void sbnet_mma_kernel(const float* __restrict__ x,
                      const float* __restrict__ mask,
                      const float* __restrict__ bias,
                      float* __restrict__ out) {
    extern __shared__ char smem[];
    const uint32_t sbase = smem_u32(smem);

    const int b   = blockIdx.x;
    const int n   = b >> 10;
    const int rem = b & (NBLK - 1);
    const int by  = rem >> 5, bx = rem & 31;
    const int t   = threadIdx.x;
    const int wid = t >> 5, lane = t & 31;
    const int y0  = by * BS, x0 = bx * BS;

    // ---- activity: one thread per element of the 16x16 gather window ----
    float mv = 0.f;
    {
        int ty = t >> 4, tx = t & 15;
        int gy = y0 - 1 + ty, gx = x0 - 1 + tx;
        if ((unsigned)gy < (unsigned)Himg && (unsigned)gx < (unsigned)Wimg)
            mv = mask[(size_t)n * Himg * Wimg + gy * Wimg + gx];
    }
    const int act = __syncthreads_or(mv > 0.5f);

    if (!act) {  // zero-fill the 14x14 block for all 64 couts
        for (int i = t; i < 64 * 14 * 7; i += TPB) {
            int co = i / 98, r2 = i - co * 98, y = r2 / 7, j = r2 - y * 7;
            float2* op = (float2*)(out + (((size_t)n * 64 + co) * Himg + y0 + y) * Wimg
                                   + x0 + 2 * j);
            *op = make_float2(0.f, 0.f);
        }
        return;
    }

    if (t < 64) *(float*)(smem + t * 4) = bias[t];

    // ---- stage X: thread t owns pixel p=t; hi/lo bf16, swizzled rows ----
    {
        const int p = t, ty = p >> 4, tx = p & 15;
        const int gy = y0 - 1 + ty, gx = x0 - 1 + tx;
        const bool inb = (unsigned)gy < (unsigned)Himg && (unsigned)gx < (unsigned)Wimg;
        const float* xp = x + (size_t)n * 64 * Himg * Wimg + (size_t)gy * Wimg + gx;
        const int prow = p * 128, p7 = p & 7;
        #pragma unroll 4
        for (int c = 0; c < 64; c++) {
            float v = inb ? xp[(size_t)c * Himg * Wimg] : 0.f;
            __nv_bfloat16 hi = __float2bfloat16(v);
            __nv_bfloat16 lo = __float2bfloat16(v - __bfloat162float(hi));
            uint32_t off = prow + ((((c >> 3) ^ p7) << 4)) + ((c & 7) << 1);
            *(uint16_t*)(smem + SM_X_HI + off) = __bfloat16_as_ushort(hi);
            *(uint16_t*)(smem + SM_X_LO + off) = __bfloat16_as_ushort(lo);
        }
    }
    // ---- stage W: raw copy of preconverted swizzled image ----
    {
        const uint4* sh = (const uint4*)g_whi;
        const uint4* sl = (const uint4*)g_wlo;
        uint4* dh = (uint4*)(smem + SM_W_HI);
        uint4* dl = (uint4*)(smem + SM_W_LO);
        for (int i = t; i < WB / 16; i += TPB) {
            dh[i] = sh[i];
            dl[i] = sl[i];
        }
    }
    __syncthreads();

    // ---- compute ----
    const int m0 = (wid & 3) * 64;         // pixel-row block
    const int n0 = (wid >> 2) * 32;        // cout block
    const int q  = lane >> 2, tq = lane & 3;

    float acc[4][4][4];
    #pragma unroll
    for (int mt = 0; mt < 4; mt++)
        #pragma unroll
        for (int nt = 0; nt < 4; nt++)
            #pragma unroll
            for (int i = 0; i < 4; i++) acc[mt][nt][i] = 0.f;

    // per-lane invariants
    const int arow_l = (lane & 15);        // A: row within m16 tile
    const int ahi    = lane >> 4;          // A: k 16B-chunk select
    const int nrow   = n0 + (lane & 7) + ((lane & 16) >> 1);  // B row (cout)
    const int bhi    = (lane >> 3) & 1;    // B: k 16B-chunk select
    const uint32_t brow_base = sbase + nrow * 128;
    const int nx7 = nrow & 7;

    #pragma unroll 1
    for (int pass = 0; pass < 3; pass++) {
        const uint32_t ab = (pass == 1) ? (uint32_t)SM_X_LO : (uint32_t)SM_X_HI;
        const uint32_t wb = (pass == 2) ? (uint32_t)SM_W_LO : (uint32_t)SM_W_HI;
        #pragma unroll 1
        for (int tap = 0; tap < 9; tap++) {
            const int shift = (tap / 3) * 16 + (tap % 3);
            uint32_t abase[4];
            int a7[4];
            #pragma unroll
            for (int mt = 0; mt < 4; mt++) {
                int rowA = m0 + mt * 16 + arow_l + shift;
                abase[mt] = sbase + ab + rowA * 128;
                a7[mt] = rowA & 7;
            }
            const uint32_t wtap = wb + tap * 8192;
            #pragma unroll
            for (int kc = 0; kc < 4; kc++) {
                uint32_t afr[4][4], bfr[4];
                #pragma unroll
                for (int mt = 0; mt < 4; mt++)
                    ldsm4(afr[mt],
                          abase[mt] + ((((kc * 2 + ahi) ^ a7[mt]) << 4)));
                ldsm4(bfr, brow_base + wtap +
                              ((((kc * 2 + bhi) ^ nx7) << 4)));
                uint32_t bfr2[4];
                {  // second pair of n8 tiles: rows nrow+16 (covered by x4 above?
                   // no: x4 loads 2 n8 tiles (n0..15 of this half). Second x4:
                }
                ldsm4(bfr2, brow_base + 16 * 128 + wtap +
                               ((((kc * 2 + bhi) ^ ((nrow + 16) & 7)) << 4)));
                #pragma unroll
                for (int mt = 0; mt < 4; mt++) {
                    mma_bf16(acc[mt][0], afr[mt], bfr + 0);
                    mma_bf16(acc[mt][1], afr[mt], bfr + 2);
                    mma_bf16(acc[mt][2], afr[mt], bfr2 + 0);
                    mma_bf16(acc[mt][3], afr[mt], bfr2 + 2);
                }
            }
        }
    }

    // ---- epilogue: bias + masked stores ----
    const float* bias_s = (const float*)smem;
    #pragma unroll
    for (int mt = 0; mt < 4; mt++) {
        const int y = (m0 >> 4) + mt;
        if (y >= 14) continue;
        #pragma unroll
        for (int nt = 0; nt < 4; nt++) {
            const int nb = n0 + nt * 8 + 2 * tq;
            const float b0 = bias_s[nb], b1 = bias_s[nb + 1];
            float* base = out + ((size_t)(n * 64 + nb) * Himg + (y0 + y)) * Wimg + x0;
            // c0,c1: x = q (always < 14)
            base[q] = acc[mt][nt][0] + b0;
            base[(size_t)Himg * Wimg + q] = acc[mt][nt][1] + b1;
            // c2,c3: x = q + 8 (valid iff q < 6)
            if (q < 6) {
                base[q + 8] = acc[mt][nt][2] + b0;
                base[(size_t)Himg * Wimg + q + 8] = acc[mt][nt][3] + b1;
            }
        }
    }
}

extern "C" void kernel_launch(void* const* d_in, const int* in_sizes, int n_in,
                              void* d_out, int out_size) {
    const float* x      = (const float*)d_in[0];
    const float* mask   = (const float*)d_in[1];
    const float* weight = (const float*)d_in[2];
    const float* bias   = (const float*)d_in[3];
    float* out = (float*)d_out;

    wconv_kernel<<<(64 * 64 * 9 + 255) / 256, 256>>>(weight);

    cudaFuncSetAttribute(sbnet_mma_kernel,
                         cudaFuncAttributeMaxDynamicSharedMemorySize, SMEM_TOTAL);
    sbnet_mma_kernel<<<4 * NBLK, TPB, SMEM_TOTAL>>>(x, mask, bias, out);
}

// round 6
// speedup vs baseline: 1.9626x; 1.4491x over previous
#include <cuda_runtime.h>
#include <cuda_bf16.h>
#include <cstdint>

// SBNet block-sparse 3x3 conv via mma.sync (HMMA) bf16-split implicit GEMM.
// R5: fused 3-way split passes — per (tap,kc) load A_hi/A_lo/B_hi/B_lo once,
// issue xh*wh + xl*wh + xh*wl into one fp32 accumulator set (LDSM traffic -33%).
// x[4][64][448][448] f32, mask[4][1][448][448], weight[64][64][3][3], bias[64],
// out[4][64][448][448]. 14x14 output blocks; active iff max(mask over 16x16
// gather window at offset -1) > 0.5.

namespace {
constexpr int Himg = 448, Wimg = 448, NBLK = 1024, TPB = 256;
constexpr int BS = 14;
constexpr int SM_X_HI = 1024;          // [0..256) bias
constexpr int XB = 256 * 128;          // 256 pixel-rows x 64ch bf16
constexpr int SM_X_LO = SM_X_HI + XB;  // 33792
constexpr int WB = 9 * 64 * 128;       // 9 taps x 64 cout rows x 64 cin bf16
constexpr int SM_W_HI = SM_X_LO + XB;  // 66560
constexpr int SM_W_LO = SM_W_HI + WB;  // 140288
constexpr int SMEM_TOTAL = SM_W_LO + WB;  // 214016
}

__device__ uint16_t g_whi[9 * 64 * 64];
__device__ uint16_t g_wlo[9 * 64 * 64];

__device__ __forceinline__ uint32_t smem_u32(const void* p) {
    uint32_t a;
    asm("{ .reg .u64 t; cvta.to.shared.u64 t, %1; cvt.u32.u64 %0, t; }"
        : "=r"(a) : "l"(p));
    return a;
}
__device__ __forceinline__ void ldsm4(uint32_t* r, uint32_t addr) {
    asm volatile("ldmatrix.sync.aligned.m8n8.x4.shared.b16 {%0,%1,%2,%3}, [%4];"
                 : "=r"(r[0]), "=r"(r[1]), "=r"(r[2]), "=r"(r[3]) : "r"(addr));
}
__device__ __forceinline__ void mma_bf16(float* d, const uint32_t* a,
                                         const uint32_t* b) {
    asm volatile(
        "mma.sync.aligned.m16n8k16.row.col.f32.bf16.bf16.f32 "
        "{%0,%1,%2,%3},{%4,%5,%6,%7},{%8,%9},{%0,%1,%2,%3};"
        : "+f"(d[0]), "+f"(d[1]), "+f"(d[2]), "+f"(d[3])
        : "r"(a[0]), "r"(a[1]), "r"(a[2]), "r"(a[3]), "r"(b[0]), "r"(b[1]));
}

// one-time: weight[o][c][ky][kx] f32 -> swizzled bf16 hi/lo, layout
// [tap][o-row(128B)][cin], 16B-chunk swizzle: chunk ^= (o&7).
__global__ void wconv_kernel(const float* __restrict__ w) {
    int i = blockIdx.x * blockDim.x + threadIdx.x;
    if (i >= 64 * 64 * 9) return;
    int o = i / 576, r = i - o * 576, c = r / 9, k = r - c * 9;
    float v = w[i];
    __nv_bfloat16 hi = __float2bfloat16(v);
    __nv_bfloat16 lo = __float2bfloat16(v - __bfloat162float(hi));
    uint32_t off16 = k * 4096 + o * 64 + ((((c >> 3) ^ (o & 7)) << 3)) + (c & 7);
    g_whi[off16] = __bfloat16_as_ushort(hi);
    g_wlo[off16] = __bfloat16_as_ushort(lo);
}

__global__ __launch_bounds__(TPB, 1)
void sbnet_mma_kernel(const float* __restrict__ x,
                      const float* __restrict__ mask,
                      const float* __restrict__ bias,
                      float* __restrict__ out) {
    extern __shared__ char smem[];
    const uint32_t sbase = smem_u32(smem);

    const int b   = blockIdx.x;
    const int n   = b >> 10;
    const int rem = b & (NBLK - 1);
    const int by  = rem >> 5, bx = rem & 31;
    const int t   = threadIdx.x;
    const int wid = t >> 5, lane = t & 31;
    const int y0  = by * BS, x0 = bx * BS;

    // ---- activity: one thread per element of the 16x16 gather window ----
    float mv = 0.f;
    {
        int ty = t >> 4, tx = t & 15;
        int gy = y0 - 1 + ty, gx = x0 - 1 + tx;
        if ((unsigned)gy < (unsigned)Himg && (unsigned)gx < (unsigned)Wimg)
            mv = mask[(size_t)n * Himg * Wimg + gy * Wimg + gx];
    }
    const int act = __syncthreads_or(mv > 0.5f);

    if (!act) {  // zero-fill the 14x14 block for all 64 couts
        for (int i = t; i < 64 * 14 * 7; i += TPB) {
            int co = i / 98, r2 = i - co * 98, y = r2 / 7, j = r2 - y * 7;
            float2* op = (float2*)(out + (((size_t)n * 64 + co) * Himg + y0 + y) * Wimg
                                   + x0 + 2 * j);
            *op = make_float2(0.f, 0.f);
        }
        return;
    }

    if (t < 64) *(float*)(smem + t * 4) = bias[t];

    // ---- stage X: thread t owns pixel p=t; hi/lo bf16, swizzled rows ----
    {
        const int p = t, ty = p >> 4, tx = p & 15;
        const int gy = y0 - 1 + ty, gx = x0 - 1 + tx;
        const bool inb = (unsigned)gy < (unsigned)Himg && (unsigned)gx < (unsigned)Wimg;
        const float* xp = x + (size_t)n * 64 * Himg * Wimg + (size_t)gy * Wimg + gx;
        const int prow = p * 128, p7 = p & 7;
        #pragma unroll 4
        for (int c = 0; c < 64; c++) {
            float v = inb ? xp[(size_t)c * Himg * Wimg] : 0.f;
            __nv_bfloat16 hi = __float2bfloat16(v);
            __nv_bfloat16 lo = __float2bfloat16(v - __bfloat162float(hi));
            uint32_t off = prow + ((((c >> 3) ^ p7) << 4)) + ((c & 7) << 1);
            *(uint16_t*)(smem + SM_X_HI + off) = __bfloat16_as_ushort(hi);
            *(uint16_t*)(smem + SM_X_LO + off) = __bfloat16_as_ushort(lo);
        }
    }
    // ---- stage W: raw copy of preconverted swizzled image ----
    {
        const uint4* sh = (const uint4*)g_whi;
        const uint4* sl = (const uint4*)g_wlo;
        uint4* dh = (uint4*)(smem + SM_W_HI);
        uint4* dl = (uint4*)(smem + SM_W_LO);
        for (int i = t; i < WB / 16; i += TPB) {
            dh[i] = sh[i];
            dl[i] = sl[i];
        }
    }
    __syncthreads();

    // ---- compute ----
    const int m0 = (wid & 3) * 64;         // pixel-row block
    const int n0 = (wid >> 2) * 32;        // cout block
    const int q  = lane >> 2, tq = lane & 3;

    float acc[4][4][4];
    #pragma unroll
    for (int mt = 0; mt < 4; mt++)
        #pragma unroll
        for (int nt = 0; nt < 4; nt++)
            #pragma unroll
            for (int i = 0; i < 4; i++) acc[mt][nt][i] = 0.f;

    // per-lane invariants
    const int arow_l = (lane & 15);        // A: row within m16 tile
    const int ahi    = lane >> 4;          // A: k 16B-chunk select
    const int nrow   = n0 + (lane & 7) + ((lane & 16) >> 1);  // B row (cout)
    const int bhi    = (lane >> 3) & 1;    // B: k 16B-chunk select
    const uint32_t brow = sbase + nrow * 128;  // (nrow+16)&7 == nrow&7
    const int nx7 = nrow & 7;

    #pragma unroll 1
    for (int tap = 0; tap < 9; tap++) {
        const int shift = (tap / 3) * 16 + (tap % 3);
        uint32_t abase[4];
        int a7[4];
        #pragma unroll
        for (int mt = 0; mt < 4; mt++) {
            int rowA = m0 + mt * 16 + arow_l + shift;
            abase[mt] = sbase + SM_X_HI + rowA * 128;
            a7[mt] = rowA & 7;
        }
        const uint32_t wt_hi = (uint32_t)SM_W_HI + tap * 8192;
        const uint32_t wt_lo = (uint32_t)SM_W_LO + tap * 8192;
        #pragma unroll 2
        for (int kc = 0; kc < 4; kc++) {
            uint32_t ah[4][4], al[4][4], bh[8], bl[8];
            #pragma unroll
            for (int mt = 0; mt < 4; mt++) {
                const uint32_t ch = (((kc * 2 + ahi) ^ a7[mt]) << 4);
                ldsm4(ah[mt], abase[mt] + ch);
                ldsm4(al[mt], abase[mt] + XB + ch);
            }
            const uint32_t cb = (((kc * 2 + bhi) ^ nx7) << 4);
            ldsm4(bh + 0, brow + wt_hi + cb);
            ldsm4(bh + 4, brow + wt_hi + 2048 + cb);
            ldsm4(bl + 0, brow + wt_lo + cb);
            ldsm4(bl + 4, brow + wt_lo + 2048 + cb);
            #pragma unroll
            for (int mt = 0; mt < 4; mt++) {
                #pragma unroll
                for (int nt = 0; nt < 4; nt++) {
                    mma_bf16(acc[mt][nt], ah[mt], bh + nt * 2);  // xh*wh
                    mma_bf16(acc[mt][nt], al[mt], bh + nt * 2);  // xl*wh
                    mma_bf16(acc[mt][nt], ah[mt], bl + nt * 2);  // xh*wl
                }
            }
        }
    }

    // ---- epilogue: bias + masked stores ----
    const float* bias_s = (const float*)smem;
    #pragma unroll
    for (int mt = 0; mt < 4; mt++) {
        const int y = (m0 >> 4) + mt;
        if (y >= 14) continue;
        #pragma unroll
        for (int nt = 0; nt < 4; nt++) {
            const int nb = n0 + nt * 8 + 2 * tq;
            const float b0 = bias_s[nb], b1 = bias_s[nb + 1];
            float* base = out + ((size_t)(n * 64 + nb) * Himg + (y0 + y)) * Wimg + x0;
            base[q] = acc[mt][nt][0] + b0;
            base[(size_t)Himg * Wimg + q] = acc[mt][nt][1] + b1;
            if (q < 6) {
                base[q + 8] = acc[mt][nt][2] + b0;
                base[(size_t)Himg * Wimg + q + 8] = acc[mt][nt][3] + b1;
            }
        }
    }
}

extern "C" void kernel_launch(void* const* d_in, const int* in_sizes, int n_in,
                              void* d_out, int out_size) {
    const float* x      = (const float*)d_in[0];
    const float* mask   = (const float*)d_in[1];
    const float* weight = (const float*)d_in[2];
    const float* bias   = (const float*)d_in[3];
    float* out = (float*)d_out;

    wconv_kernel<<<(64 * 64 * 9 + 255) / 256, 256>>>(weight);

    cudaFuncSetAttribute(sbnet_mma_kernel,
                         cudaFuncAttributeMaxDynamicSharedMemorySize, SMEM_TOTAL);
    sbnet_mma_kernel<<<4 * NBLK, TPB, SMEM_TOTAL>>>(x, mask, bias, out);
}

// round 7
// speedup vs baseline: 2.0323x; 1.0355x over previous
#include <cuda_runtime.h>
#include <cuda_bf16.h>
#include <cstdint>

// SBNet block-sparse 3x3 conv via mma.sync (HMMA) bf16-split implicit GEMM.
// R6: 14 warps (448 thr), M=224 valid rows only (skip y>=14 garbage rows),
// warp tile M=32 x N=32. Fused 3-product split: xh*wh + xl*wh + xh*wl.
// x[4][64][448][448] f32, mask[4][1][448][448], weight[64][64][3][3], bias[64],
// out[4][64][448][448]. 14x14 output blocks; active iff max(mask over 16x16
// gather window at offset -1) > 0.5.

namespace {
constexpr int Himg = 448, Wimg = 448, NBLK = 1024, TPB = 448;
constexpr int BS = 14;
constexpr int SM_X_HI = 1024;          // [0..256) bias
constexpr int XB = 256 * 128;          // 256 pixel-rows x 64ch bf16
constexpr int SM_X_LO = SM_X_HI + XB;  // 33792
constexpr int WB = 9 * 64 * 128;       // 9 taps x 64 cout rows x 64 cin bf16
constexpr int SM_W_HI = SM_X_LO + XB;  // 66560
constexpr int SM_W_LO = SM_W_HI + WB;  // 140288
constexpr int SMEM_TOTAL = SM_W_LO + WB;  // 214016
}

__device__ uint16_t g_whi[9 * 64 * 64];
__device__ uint16_t g_wlo[9 * 64 * 64];

__device__ __forceinline__ uint32_t smem_u32(const void* p) {
    uint32_t a;
    asm("{ .reg .u64 t; cvta.to.shared.u64 t, %1; cvt.u32.u64 %0, t; }"
        : "=r"(a) : "l"(p));
    return a;
}
__device__ __forceinline__ void ldsm4(uint32_t* r, uint32_t addr) {
    asm volatile("ldmatrix.sync.aligned.m8n8.x4.shared.b16 {%0,%1,%2,%3}, [%4];"
                 : "=r"(r[0]), "=r"(r[1]), "=r"(r[2]), "=r"(r[3]) : "r"(addr));
}
__device__ __forceinline__ void mma_bf16(float* d, const uint32_t* a,
                                         const uint32_t* b) {
    asm volatile(
        "mma.sync.aligned.m16n8k16.row.col.f32.bf16.bf16.f32 "
        "{%0,%1,%2,%3},{%4,%5,%6,%7},{%8,%9},{%0,%1,%2,%3};"
        : "+f"(d[0]), "+f"(d[1]), "+f"(d[2]), "+f"(d[3])
        : "r"(a[0]), "r"(a[1]), "r"(a[2]), "r"(a[3]), "r"(b[0]), "r"(b[1]));
}

// one-time: weight[o][c][ky][kx] f32 -> swizzled bf16 hi/lo, layout
// [tap][o-row(128B)][cin], 16B-chunk swizzle: chunk ^= (o&7).
__global__ void wconv_kernel(const float* __restrict__ w) {
    int i = blockIdx.x * blockDim.x + threadIdx.x;
    if (i >= 64 * 64 * 9) return;
    int o = i / 576, r = i - o * 576, c = r / 9, k = r - c * 9;
    float v = w[i];
    __nv_bfloat16 hi = __float2bfloat16(v);
    __nv_bfloat16 lo = __float2bfloat16(v - __bfloat162float(hi));
    uint32_t off16 = k * 4096 + o * 64 + ((((c >> 3) ^ (o & 7)) << 3)) + (c & 7);
    g_whi[off16] = __bfloat16_as_ushort(hi);
    g_wlo[off16] = __bfloat16_as_ushort(lo);
}

__global__ __launch_bounds__(TPB, 1)
void sbnet_mma_kernel(const float* __restrict__ x,
                      const float* __restrict__ mask,
                      const float* __restrict__ bias,
                      float* __restrict__ out) {
    extern __shared__ char smem[];
    const uint32_t sbase = smem_u32(smem);

    const int b   = blockIdx.x;
    const int n   = b >> 10;
    const int rem = b & (NBLK - 1);
    const int by  = rem >> 5, bx = rem & 31;
    const int t   = threadIdx.x;
    const int wid = t >> 5, lane = t & 31;
    const int y0  = by * BS, x0 = bx * BS;

    // ---- activity: threads 0..255 check the 16x16 gather window ----
    float mv = 0.f;
    if (t < 256) {
        int ty = t >> 4, tx = t & 15;
        int gy = y0 - 1 + ty, gx = x0 - 1 + tx;
        if ((unsigned)gy < (unsigned)Himg && (unsigned)gx < (unsigned)Wimg)
            mv = mask[(size_t)n * Himg * Wimg + gy * Wimg + gx];
    }
    const int act = __syncthreads_or(mv > 0.5f);

    if (!act) {  // zero-fill the 14x14 block for all 64 couts
        for (int i = t; i < 64 * 14 * 7; i += TPB) {
            int co = i / 98, r2 = i - co * 98, y = r2 / 7, j = r2 - y * 7;
            float2* op = (float2*)(out + (((size_t)n * 64 + co) * Himg + y0 + y) * Wimg
                                   + x0 + 2 * j);
            *op = make_float2(0.f, 0.f);
        }
        return;
    }

    if (t < 64) *(float*)(smem + t * 4) = bias[t];

    // ---- stage X: threads 0..255 own pixel p=t; hi/lo bf16, swizzled ----
    if (t < 256) {
        const int p = t, ty = p >> 4, tx = p & 15;
        const int gy = y0 - 1 + ty, gx = x0 - 1 + tx;
        const bool inb = (unsigned)gy < (unsigned)Himg && (unsigned)gx < (unsigned)Wimg;
        const float* xp = x + (size_t)n * 64 * Himg * Wimg + (size_t)gy * Wimg + gx;
        const int prow = p * 128, p7 = p & 7;
        #pragma unroll 4
        for (int c = 0; c < 64; c++) {
            float v = inb ? xp[(size_t)c * Himg * Wimg] : 0.f;
            __nv_bfloat16 hi = __float2bfloat16(v);
            __nv_bfloat16 lo = __float2bfloat16(v - __bfloat162float(hi));
            uint32_t off = prow + ((((c >> 3) ^ p7) << 4)) + ((c & 7) << 1);
            *(uint16_t*)(smem + SM_X_HI + off) = __bfloat16_as_ushort(hi);
            *(uint16_t*)(smem + SM_X_LO + off) = __bfloat16_as_ushort(lo);
        }
    }
    // ---- stage W: raw copy of preconverted swizzled image ----
    {
        const uint4* sh = (const uint4*)g_whi;
        const uint4* sl = (const uint4*)g_wlo;
        uint4* dh = (uint4*)(smem + SM_W_HI);
        uint4* dl = (uint4*)(smem + SM_W_LO);
        for (int i = t; i < WB / 16; i += TPB) {
            dh[i] = sh[i];
            dl[i] = sl[i];
        }
    }
    __syncthreads();

    // ---- compute: warp = (mblk 0..6) x (nhalf 0..1); tile M=32, N=32 ----
    const int nhalf = wid / 7;
    const int mblk  = wid - nhalf * 7;
    const int m0 = mblk * 32;              // pixel-row block (rows < 224 valid)
    const int n0 = nhalf * 32;             // cout block
    const int q  = lane >> 2, tq = lane & 3;

    float acc[2][4][4];
    #pragma unroll
    for (int mt = 0; mt < 2; mt++)
        #pragma unroll
        for (int nt = 0; nt < 4; nt++)
            #pragma unroll
            for (int i = 0; i < 4; i++) acc[mt][nt][i] = 0.f;

    // per-lane invariants
    const int arow_l = (lane & 15);        // A: row within m16 tile
    const int ahi    = lane >> 4;          // A: k 16B-chunk select
    const int nrow   = n0 + (lane & 7) + ((lane & 16) >> 1);  // B row (cout)
    const int bhi    = (lane >> 3) & 1;    // B: k 16B-chunk select
    const uint32_t brow = sbase + nrow * 128;  // (nrow+16)&7 == nrow&7
    const int nx7 = nrow & 7;

    #pragma unroll 1
    for (int tap = 0; tap < 9; tap++) {
        const int shift = (tap / 3) * 16 + (tap % 3);
        uint32_t abase[2];
        int a7[2];
        #pragma unroll
        for (int mt = 0; mt < 2; mt++) {
            int rowA = m0 + mt * 16 + arow_l + shift;
            abase[mt] = sbase + SM_X_HI + rowA * 128;
            a7[mt] = rowA & 7;
        }
        const uint32_t wt_hi = (uint32_t)SM_W_HI + tap * 8192;
        const uint32_t wt_lo = (uint32_t)SM_W_LO + tap * 8192;
        #pragma unroll 2
        for (int kc = 0; kc < 4; kc++) {
            uint32_t ah[2][4], al[2][4], bh[8], bl[8];
            #pragma unroll
            for (int mt = 0; mt < 2; mt++) {
                const uint32_t ch = (((kc * 2 + ahi) ^ a7[mt]) << 4);
                ldsm4(ah[mt], abase[mt] + ch);
                ldsm4(al[mt], abase[mt] + XB + ch);
            }
            const uint32_t cb = (((kc * 2 + bhi) ^ nx7) << 4);
            ldsm4(bh + 0, brow + wt_hi + cb);
            ldsm4(bh + 4, brow + wt_hi + 2048 + cb);
            ldsm4(bl + 0, brow + wt_lo + cb);
            ldsm4(bl + 4, brow + wt_lo + 2048 + cb);
            #pragma unroll
            for (int mt = 0; mt < 2; mt++) {
                #pragma unroll
                for (int nt = 0; nt < 4; nt++) {
                    mma_bf16(acc[mt][nt], ah[mt], bh + nt * 2);  // xh*wh
                    mma_bf16(acc[mt][nt], al[mt], bh + nt * 2);  // xl*wh
                    mma_bf16(acc[mt][nt], ah[mt], bl + nt * 2);  // xh*wl
                }
            }
        }
    }

    // ---- epilogue: bias + masked stores (y always < 14 by construction) ----
    const float* bias_s = (const float*)smem;
    #pragma unroll
    for (int mt = 0; mt < 2; mt++) {
        const int y = mblk * 2 + mt;
        #pragma unroll
        for (int nt = 0; nt < 4; nt++) {
            const int nb = n0 + nt * 8 + 2 * tq;
            const float b0 = bias_s[nb], b1 = bias_s[nb + 1];
            float* base = out + ((size_t)(n * 64 + nb) * Himg + (y0 + y)) * Wimg + x0;
            base[q] = acc[mt][nt][0] + b0;
            base[(size_t)Himg * Wimg + q] = acc[mt][nt][1] + b1;
            if (q < 6) {
                base[q + 8] = acc[mt][nt][2] + b0;
                base[(size_t)Himg * Wimg + q + 8] = acc[mt][nt][3] + b1;
            }
        }
    }
}

extern "C" void kernel_launch(void* const* d_in, const int* in_sizes, int n_in,
                              void* d_out, int out_size) {
    const float* x      = (const float*)d_in[0];
    const float* mask   = (const float*)d_in[1];
    const float* weight = (const float*)d_in[2];
    const float* bias   = (const float*)d_in[3];
    float* out = (float*)d_out;

    wconv_kernel<<<(64 * 64 * 9 + 255) / 256, 256>>>(weight);

    cudaFuncSetAttribute(sbnet_mma_kernel,
                         cudaFuncAttributeMaxDynamicSharedMemorySize, SMEM_TOTAL);
    sbnet_mma_kernel<<<4 * NBLK, TPB, SMEM_TOTAL>>>(x, mask, bias, out);
}

// round 8
// speedup vs baseline: 2.1128x; 1.0396x over previous
#include <cuda_runtime.h>
#include <cuda_bf16.h>
#include <cstdint>

// SBNet block-sparse 3x3 conv via mma.sync (HMMA) bf16-split implicit GEMM.
// R7: software-pipelined fragment loads (double buffer across flattened
// (tap,kc) iterations) + product-major MMA order to break accumulator RAW
// chains. 14 warps, warp tile M=32 x N=32, valid 224 M-rows only.
// Fused 3-product split: xh*wh + xl*wh + xh*wl (fp32 accumulate).

namespace {
constexpr int Himg = 448, Wimg = 448, NBLK = 1024, TPB = 448;
constexpr int BS = 14;
constexpr int SM_X_HI = 1024;          // [0..256) bias
constexpr int XB = 256 * 128;          // 256 pixel-rows x 64ch bf16
constexpr int SM_X_LO = SM_X_HI + XB;  // 33792
constexpr int WB = 9 * 64 * 128;       // 9 taps x 64 cout rows x 64 cin bf16
constexpr int SM_W_HI = SM_X_LO + XB;  // 66560
constexpr int SM_W_LO = SM_W_HI + WB;  // 140288
constexpr int SMEM_TOTAL = SM_W_LO + WB;  // 214016
}

__device__ uint16_t g_whi[9 * 64 * 64];
__device__ uint16_t g_wlo[9 * 64 * 64];

__device__ __forceinline__ uint32_t smem_u32(const void* p) {
    uint32_t a;
    asm("{ .reg .u64 t; cvta.to.shared.u64 t, %1; cvt.u32.u64 %0, t; }"
        : "=r"(a) : "l"(p));
    return a;
}
__device__ __forceinline__ void ldsm4(uint32_t* r, uint32_t addr) {
    asm volatile("ldmatrix.sync.aligned.m8n8.x4.shared.b16 {%0,%1,%2,%3}, [%4];"
                 : "=r"(r[0]), "=r"(r[1]), "=r"(r[2]), "=r"(r[3]) : "r"(addr));
}
__device__ __forceinline__ void mma_bf16(float* d, const uint32_t* a,
                                         const uint32_t* b) {
    asm volatile(
        "mma.sync.aligned.m16n8k16.row.col.f32.bf16.bf16.f32 "
        "{%0,%1,%2,%3},{%4,%5,%6,%7},{%8,%9},{%0,%1,%2,%3};"
        : "+f"(d[0]), "+f"(d[1]), "+f"(d[2]), "+f"(d[3])
        : "r"(a[0]), "r"(a[1]), "r"(a[2]), "r"(a[3]), "r"(b[0]), "r"(b[1]));
}

// one-time: weight[o][c][ky][kx] f32 -> swizzled bf16 hi/lo, layout
// [tap][o-row(128B)][cin], 16B-chunk swizzle: chunk ^= (o&7).
__global__ void wconv_kernel(const float* __restrict__ w) {
    int i = blockIdx.x * blockDim.x + threadIdx.x;
    if (i >= 64 * 64 * 9) return;
    int o = i / 576, r = i - o * 576, c = r / 9, k = r - c * 9;
    float v = w[i];
    __nv_bfloat16 hi = __float2bfloat16(v);
    __nv_bfloat16 lo = __float2bfloat16(v - __bfloat162float(hi));
    uint32_t off16 = k * 4096 + o * 64 + ((((c >> 3) ^ (o & 7)) << 3)) + (c & 7);
    g_whi[off16] = __bfloat16_as_ushort(hi);
    g_wlo[off16] = __bfloat16_as_ushort(lo);
}

__global__ __launch_bounds__(TPB, 1)
void sbnet_mma_kernel(const float* __restrict__ x,
                      const float* __restrict__ mask,
                      const float* __restrict__ bias,
                      float* __restrict__ out) {
    extern __shared__ char smem[];
    const uint32_t sbase = smem_u32(smem);

    const int b   = blockIdx.x;
    const int n   = b >> 10;
    const int rem = b & (NBLK - 1);
    const int by  = rem >> 5, bx = rem & 31;
    const int t   = threadIdx.x;
    const int wid = t >> 5, lane = t & 31;
    const int y0  = by * BS, x0 = bx * BS;

    // ---- activity: threads 0..255 check the 16x16 gather window ----
    float mv = 0.f;
    if (t < 256) {
        int ty = t >> 4, tx = t & 15;
        int gy = y0 - 1 + ty, gx = x0 - 1 + tx;
        if ((unsigned)gy < (unsigned)Himg && (unsigned)gx < (unsigned)Wimg)
            mv = mask[(size_t)n * Himg * Wimg + gy * Wimg + gx];
    }
    const int act = __syncthreads_or(mv > 0.5f);

    if (!act) {  // zero-fill the 14x14 block for all 64 couts
        for (int i = t; i < 64 * 14 * 7; i += TPB) {
            int co = i / 98, r2 = i - co * 98, y = r2 / 7, j = r2 - y * 7;
            float2* op = (float2*)(out + (((size_t)n * 64 + co) * Himg + y0 + y) * Wimg
                                   + x0 + 2 * j);
            *op = make_float2(0.f, 0.f);
        }
        return;
    }

    // ---- staging: threads 0..255 stage X; threads 256..447 copy W ----
    if (t < 256) {
        if (t < 64) *(float*)(smem + t * 4) = bias[t];
        const int p = t, ty = p >> 4, tx = p & 15;
        const int gy = y0 - 1 + ty, gx = x0 - 1 + tx;
        const bool inb = (unsigned)gy < (unsigned)Himg && (unsigned)gx < (unsigned)Wimg;
        const float* xp = x + (size_t)n * 64 * Himg * Wimg + (size_t)gy * Wimg + gx;
        const int prow = p * 128, p7 = p & 7;
        #pragma unroll 4
        for (int c = 0; c < 64; c++) {
            float v = inb ? xp[(size_t)c * Himg * Wimg] : 0.f;
            __nv_bfloat16 hi = __float2bfloat16(v);
            __nv_bfloat16 lo = __float2bfloat16(v - __bfloat162float(hi));
            uint32_t off = prow + ((((c >> 3) ^ p7) << 4)) + ((c & 7) << 1);
            *(uint16_t*)(smem + SM_X_HI + off) = __bfloat16_as_ushort(hi);
            *(uint16_t*)(smem + SM_X_LO + off) = __bfloat16_as_ushort(lo);
        }
    } else {
        const uint4* sh = (const uint4*)g_whi;
        const uint4* sl = (const uint4*)g_wlo;
        uint4* dh = (uint4*)(smem + SM_W_HI);
        uint4* dl = (uint4*)(smem + SM_W_LO);
        for (int i = t - 256; i < WB / 16; i += 192) {
            dh[i] = sh[i];
            dl[i] = sl[i];
        }
    }
    __syncthreads();

    // ---- compute: warp = (mblk 0..6) x (nhalf 0..1); tile M=32, N=32 ----
    const int nhalf = wid / 7;
    const int mblk  = wid - nhalf * 7;
    const int m0 = mblk * 32;              // pixel-row block (rows < 224 valid)
    const int n0 = nhalf * 32;             // cout block
    const int q  = lane >> 2, tq = lane & 3;

    float acc[2][4][4];
    #pragma unroll
    for (int mt = 0; mt < 2; mt++)
        #pragma unroll
        for (int nt = 0; nt < 4; nt++)
            #pragma unroll
            for (int i = 0; i < 4; i++) acc[mt][nt][i] = 0.f;

    // per-lane invariants
    const int arow_l = (lane & 15);        // A: row within m16 tile
    const int ahi    = lane >> 4;          // A: k 16B-chunk select
    const int nrow   = n0 + (lane & 7) + ((lane & 16) >> 1);  // B row (cout)
    const int bhi    = (lane >> 3) & 1;    // B: k 16B-chunk select
    const uint32_t brow = sbase + nrow * 128;  // (nrow+16)&7 == nrow&7
    const int nx7 = nrow & 7;

    // fragment loader for flattened iteration it = tap*4 + kc
    auto ldfr = [&](int it, uint32_t (*ah)[4], uint32_t (*al)[4],
                    uint32_t* bh, uint32_t* bl) {
        const int tap = it >> 2, kc = it & 3;
        const int ky = tap / 3;
        const int shift = ky * 16 + (tap - ky * 3);
        const uint32_t cb = (uint32_t)(((kc * 2 + bhi) ^ nx7) << 4);
        const uint32_t bha = brow + (uint32_t)SM_W_HI + tap * 8192 + cb;
        const uint32_t bla = bha + (uint32_t)(SM_W_LO - SM_W_HI);
        ldsm4(bh + 0, bha);
        ldsm4(bh + 4, bha + 2048);
        ldsm4(bl + 0, bla);
        ldsm4(bl + 4, bla + 2048);
        #pragma unroll
        for (int mt = 0; mt < 2; mt++) {
            const int rowA = m0 + mt * 16 + arow_l + shift;
            const uint32_t ab = sbase + (uint32_t)SM_X_HI + rowA * 128;
            const uint32_t ch = (uint32_t)(((kc * 2 + ahi) ^ (rowA & 7)) << 4);
            ldsm4(ah[mt], ab + ch);
            ldsm4(al[mt], ab + XB + ch);
        }
    };

    uint32_t ahb[2][2][4], alb[2][2][4], bhb[2][8], blb[2][8];
    ldfr(0, ahb[0], alb[0], bhb[0], blb[0]);

    #pragma unroll 2
    for (int it = 0; it < 36; it++) {
        const int cur = it & 1, nxt = cur ^ 1;
        if (it < 35) ldfr(it + 1, ahb[nxt], alb[nxt], bhb[nxt], blb[nxt]);
        // product-major: 8 independent MMAs between same-acc reuses
        #pragma unroll
        for (int mt = 0; mt < 2; mt++)
            #pragma unroll
            for (int nt = 0; nt < 4; nt++)
                mma_bf16(acc[mt][nt], ahb[cur][mt], bhb[cur] + nt * 2);
        #pragma unroll
        for (int mt = 0; mt < 2; mt++)
            #pragma unroll
            for (int nt = 0; nt < 4; nt++)
                mma_bf16(acc[mt][nt], alb[cur][mt], bhb[cur] + nt * 2);
        #pragma unroll
        for (int mt = 0; mt < 2; mt++)
            #pragma unroll
            for (int nt = 0; nt < 4; nt++)
                mma_bf16(acc[mt][nt], ahb[cur][mt], blb[cur] + nt * 2);
    }

    // ---- epilogue: bias + masked stores (y always < 14 by construction) ----
    const float* bias_s = (const float*)smem;
    #pragma unroll
    for (int mt = 0; mt < 2; mt++) {
        const int y = mblk * 2 + mt;
        #pragma unroll
        for (int nt = 0; nt < 4; nt++) {
            const int nb = n0 + nt * 8 + 2 * tq;
            const float b0 = bias_s[nb], b1 = bias_s[nb + 1];
            float* base = out + ((size_t)(n * 64 + nb) * Himg + (y0 + y)) * Wimg + x0;
            base[q] = acc[mt][nt][0] + b0;
            base[(size_t)Himg * Wimg + q] = acc[mt][nt][1] + b1;
            if (q < 6) {
                base[q + 8] = acc[mt][nt][2] + b0;
                base[(size_t)Himg * Wimg + q + 8] = acc[mt][nt][3] + b1;
            }
        }
    }
}

extern "C" void kernel_launch(void* const* d_in, const int* in_sizes, int n_in,
                              void* d_out, int out_size) {
    const float* x      = (const float*)d_in[0];
    const float* mask   = (const float*)d_in[1];
    const float* weight = (const float*)d_in[2];
    const float* bias   = (const float*)d_in[3];
    float* out = (float*)d_out;

    wconv_kernel<<<(64 * 64 * 9 + 255) / 256, 256>>>(weight);

    cudaFuncSetAttribute(sbnet_mma_kernel,
                         cudaFuncAttributeMaxDynamicSharedMemorySize, SMEM_TOTAL);
    sbnet_mma_kernel<<<4 * NBLK, TPB, SMEM_TOTAL>>>(x, mask, bias, out);
}

// round 9
// speedup vs baseline: 2.5945x; 1.2280x over previous
#include <cuda_runtime.h>
#include <cuda_bf16.h>
#include <cstdint>

// SBNet block-sparse 3x3 conv via mma.sync (HMMA) bf16-split implicit GEMM.
// R8: occupancy attack — 896 threads / 28 warps per CTA (7 per SMSP), warp
// tile M=16 (one output y-row) x N=32, single-buffered fragments (~65 regs),
// fused 3-product split xh*wh + xl*wh + xh*wl, product-major MMA order.
// x[4][64][448][448] f32, mask[4][1][448][448], weight[64][64][3][3], bias[64],
// out[4][64][448][448]. 14x14 output blocks; active iff max(mask over 16x16
// gather window at offset -1) > 0.5.

namespace {
constexpr int Himg = 448, Wimg = 448, NBLK = 1024, TPB = 896;
constexpr int BS = 14;
constexpr int SM_X_HI = 1024;          // [0..256) bias
constexpr int XB = 256 * 128;          // 256 pixel-rows x 64ch bf16
constexpr int SM_X_LO = SM_X_HI + XB;  // 33792
constexpr int WB = 9 * 64 * 128;       // 9 taps x 64 cout rows x 64 cin bf16
constexpr int SM_W_HI = SM_X_LO + XB;  // 66560
constexpr int SM_W_LO = SM_W_HI + WB;  // 140288
constexpr int SMEM_TOTAL = SM_W_LO + WB;  // 214016
}

__device__ uint16_t g_whi[9 * 64 * 64];
__device__ uint16_t g_wlo[9 * 64 * 64];

__device__ __forceinline__ uint32_t smem_u32(const void* p) {
    uint32_t a;
    asm("{ .reg .u64 t; cvta.to.shared.u64 t, %1; cvt.u32.u64 %0, t; }"
        : "=r"(a) : "l"(p));
    return a;
}
__device__ __forceinline__ void ldsm4(uint32_t* r, uint32_t addr) {
    asm volatile("ldmatrix.sync.aligned.m8n8.x4.shared.b16 {%0,%1,%2,%3}, [%4];"
                 : "=r"(r[0]), "=r"(r[1]), "=r"(r[2]), "=r"(r[3]) : "r"(addr));
}
__device__ __forceinline__ void mma_bf16(float* d, const uint32_t* a,
                                         const uint32_t* b) {
    asm volatile(
        "mma.sync.aligned.m16n8k16.row.col.f32.bf16.bf16.f32 "
        "{%0,%1,%2,%3},{%4,%5,%6,%7},{%8,%9},{%0,%1,%2,%3};"
        : "+f"(d[0]), "+f"(d[1]), "+f"(d[2]), "+f"(d[3])
        : "r"(a[0]), "r"(a[1]), "r"(a[2]), "r"(a[3]), "r"(b[0]), "r"(b[1]));
}

// one-time: weight[o][c][ky][kx] f32 -> swizzled bf16 hi/lo, layout
// [tap][o-row(128B)][cin], 16B-chunk swizzle: chunk ^= (o&7).
__global__ void wconv_kernel(const float* __restrict__ w) {
    int i = blockIdx.x * blockDim.x + threadIdx.x;
    if (i >= 64 * 64 * 9) return;
    int o = i / 576, r = i - o * 576, c = r / 9, k = r - c * 9;
    float v = w[i];
    __nv_bfloat16 hi = __float2bfloat16(v);
    __nv_bfloat16 lo = __float2bfloat16(v - __bfloat162float(hi));
    uint32_t off16 = k * 4096 + o * 64 + ((((c >> 3) ^ (o & 7)) << 3)) + (c & 7);
    g_whi[off16] = __bfloat16_as_ushort(hi);
    g_wlo[off16] = __bfloat16_as_ushort(lo);
}

__global__ __launch_bounds__(TPB, 1)
void sbnet_mma_kernel(const float* __restrict__ x,
                      const float* __restrict__ mask,
                      const float* __restrict__ bias,
                      float* __restrict__ out) {
    extern __shared__ char smem[];
    const uint32_t sbase = smem_u32(smem);

    const int b   = blockIdx.x;
    const int n   = b >> 10;
    const int rem = b & (NBLK - 1);
    const int by  = rem >> 5, bx = rem & 31;
    const int t   = threadIdx.x;
    const int wid = t >> 5, lane = t & 31;
    const int y0  = by * BS, x0 = bx * BS;

    // ---- activity: threads 0..255 check the 16x16 gather window ----
    float mv = 0.f;
    if (t < 256) {
        int ty = t >> 4, tx = t & 15;
        int gy = y0 - 1 + ty, gx = x0 - 1 + tx;
        if ((unsigned)gy < (unsigned)Himg && (unsigned)gx < (unsigned)Wimg)
            mv = mask[(size_t)n * Himg * Wimg + gy * Wimg + gx];
    }
    const int act = __syncthreads_or(mv > 0.5f);

    if (!act) {  // zero-fill the 14x14 block for all 64 couts
        for (int i = t; i < 64 * 14 * 7; i += TPB) {
            int co = i / 98, r2 = i - co * 98, y = r2 / 7, j = r2 - y * 7;
            float2* op = (float2*)(out + (((size_t)n * 64 + co) * Himg + y0 + y) * Wimg
                                   + x0 + 2 * j);
            *op = make_float2(0.f, 0.f);
        }
        return;
    }

    // ---- staging: t<512 stage X (half the channels each); t>=512 copy W ----
    if (t < 512) {
        if (t < 64) *(float*)(smem + t * 4) = bias[t];
        const int p = t & 255, cb = (t >> 8) * 32;
        const int ty = p >> 4, tx = p & 15;
        const int gy = y0 - 1 + ty, gx = x0 - 1 + tx;
        const bool inb = (unsigned)gy < (unsigned)Himg && (unsigned)gx < (unsigned)Wimg;
        const float* xp = x + ((size_t)n * 64 + cb) * Himg * Wimg
                          + (size_t)gy * Wimg + gx;
        const int prow = p * 128, p7 = p & 7;
        #pragma unroll 4
        for (int ci = 0; ci < 32; ci++) {
            const int c = cb + ci;
            float v = inb ? xp[(size_t)ci * Himg * Wimg] : 0.f;
            __nv_bfloat16 hi = __float2bfloat16(v);
            __nv_bfloat16 lo = __float2bfloat16(v - __bfloat162float(hi));
            uint32_t off = prow + ((((c >> 3) ^ p7) << 4)) + ((c & 7) << 1);
            *(uint16_t*)(smem + SM_X_HI + off) = __bfloat16_as_ushort(hi);
            *(uint16_t*)(smem + SM_X_LO + off) = __bfloat16_as_ushort(lo);
        }
    } else {
        const uint4* sh = (const uint4*)g_whi;
        const uint4* sl = (const uint4*)g_wlo;
        uint4* dh = (uint4*)(smem + SM_W_HI);
        uint4* dl = (uint4*)(smem + SM_W_LO);
        for (int i = t - 512; i < WB / 16; i += 384) {
            dh[i] = sh[i];
            dl[i] = sl[i];
        }
    }
    __syncthreads();

    // ---- compute: warp = (mw 0..13) x (nhalf 0..1); tile M=16, N=32 ----
    const int nhalf = wid / 14;
    const int mw    = wid - nhalf * 14;    // output y-row = mw
    const int m0 = mw * 16;                // pixel rows [m0, m0+16) : y=mw
    const int n0 = nhalf * 32;             // cout block
    const int q  = lane >> 2, tq = lane & 3;

    float acc[4][4];
    #pragma unroll
    for (int nt = 0; nt < 4; nt++)
        #pragma unroll
        for (int i = 0; i < 4; i++) acc[nt][i] = 0.f;

    // per-lane invariants
    const int arow_l = (lane & 15);        // A: row within m16 tile
    const int ahi    = lane >> 4;          // A: k 16B-chunk select
    const int nrow   = n0 + (lane & 7) + ((lane & 16) >> 1);  // B row (cout)
    const int bhi    = (lane >> 3) & 1;    // B: k 16B-chunk select
    const uint32_t brow = sbase + nrow * 128;  // (nrow+16)&7 == nrow&7
    const int nx7 = nrow & 7;

    #pragma unroll 1
    for (int tap = 0; tap < 9; tap++) {
        const int ky = tap / 3;
        const int shift = ky * 16 + (tap - ky * 3);
        const int rowA = m0 + arow_l + shift;
        const uint32_t abase = sbase + (uint32_t)SM_X_HI + rowA * 128;
        const int a7 = rowA & 7;
        const uint32_t wt_hi = (uint32_t)SM_W_HI + tap * 8192;
        #pragma unroll
        for (int kc = 0; kc < 4; kc++) {
            uint32_t ah[4], al[4], bh[8], bl[8];
            const uint32_t ch = (((kc * 2 + ahi) ^ a7) << 4);
            ldsm4(ah, abase + ch);
            ldsm4(al, abase + XB + ch);
            const uint32_t cb = (((kc * 2 + bhi) ^ nx7) << 4);
            const uint32_t bha = brow + wt_hi + cb;
            ldsm4(bh + 0, bha);
            ldsm4(bh + 4, bha + 2048);
            ldsm4(bl + 0, bha + (uint32_t)(SM_W_LO - SM_W_HI));
            ldsm4(bl + 4, bha + (uint32_t)(SM_W_LO - SM_W_HI) + 2048);
            // product-major: 4 independent MMAs between same-acc reuses
            #pragma unroll
            for (int nt = 0; nt < 4; nt++) mma_bf16(acc[nt], ah, bh + nt * 2);
            #pragma unroll
            for (int nt = 0; nt < 4; nt++) mma_bf16(acc[nt], al, bh + nt * 2);
            #pragma unroll
            for (int nt = 0; nt < 4; nt++) mma_bf16(acc[nt], ah, bl + nt * 2);
        }
    }

    // ---- epilogue: bias + masked stores (y = mw < 14 by construction) ----
    const float* bias_s = (const float*)smem;
    {
        const int y = mw;
        #pragma unroll
        for (int nt = 0; nt < 4; nt++) {
            const int nb = n0 + nt * 8 + 2 * tq;
            const float b0 = bias_s[nb], b1 = bias_s[nb + 1];
            float* base = out + ((size_t)(n * 64 + nb) * Himg + (y0 + y)) * Wimg + x0;
            base[q] = acc[nt][0] + b0;
            base[(size_t)Himg * Wimg + q] = acc[nt][1] + b1;
            if (q < 6) {
                base[q + 8] = acc[nt][2] + b0;
                base[(size_t)Himg * Wimg + q + 8] = acc[nt][3] + b1;
            }
        }
    }
}

extern "C" void kernel_launch(void* const* d_in, const int* in_sizes, int n_in,
                              void* d_out, int out_size) {
    const float* x      = (const float*)d_in[0];
    const float* mask   = (const float*)d_in[1];
    const float* weight = (const float*)d_in[2];
    const float* bias   = (const float*)d_in[3];
    float* out = (float*)d_out;

    wconv_kernel<<<(64 * 64 * 9 + 255) / 256, 256>>>(weight);

    cudaFuncSetAttribute(sbnet_mma_kernel,
                         cudaFuncAttributeMaxDynamicSharedMemorySize, SMEM_TOTAL);
    sbnet_mma_kernel<<<4 * NBLK, TPB, SMEM_TOTAL>>>(x, mask, bias, out);
}

// round 10
// speedup vs baseline: 3.2422x; 1.2496x over previous
#include <cuda_runtime.h>
#include <cuda_fp16.h>
#include <cstdint>

// SBNet block-sparse 3x3 conv via mma.sync (HMMA) fp16-split implicit GEMM.
// R9: 2-product fp16 split — x = xh + xl (fp16 pair, ~exact), w = fp16 single;
// out = xh*w + xl*w (fp32 accumulate). Dropped term x*wl ~ 2^-12 relative.
// 896 threads / 28 warps, warp tile M=16 x N=32, SMEM 140KB.
// x[4][64][448][448] f32, mask[4][1][448][448], weight[64][64][3][3], bias[64],
// out[4][64][448][448]. 14x14 output blocks; active iff max(mask over 16x16
// gather window at offset -1) > 0.5.

namespace {
constexpr int Himg = 448, Wimg = 448, NBLK = 1024, TPB = 896;
constexpr int BS = 14;
constexpr int SM_X_HI = 1024;          // [0..256) bias
constexpr int XB = 256 * 128;          // 256 pixel-rows x 64ch fp16
constexpr int SM_X_LO = SM_X_HI + XB;  // 33792
constexpr int WB = 9 * 64 * 128;       // 9 taps x 64 cout rows x 64 cin fp16
constexpr int SM_W = SM_X_LO + XB;     // 66560
constexpr int SMEM_TOTAL = SM_W + WB;  // 140288
}

__device__ uint16_t g_w[9 * 64 * 64];

__device__ __forceinline__ uint32_t smem_u32(const void* p) {
    uint32_t a;
    asm("{ .reg .u64 t; cvta.to.shared.u64 t, %1; cvt.u32.u64 %0, t; }"
        : "=r"(a) : "l"(p));
    return a;
}
__device__ __forceinline__ void ldsm4(uint32_t* r, uint32_t addr) {
    asm volatile("ldmatrix.sync.aligned.m8n8.x4.shared.b16 {%0,%1,%2,%3}, [%4];"
                 : "=r"(r[0]), "=r"(r[1]), "=r"(r[2]), "=r"(r[3]) : "r"(addr));
}
__device__ __forceinline__ void mma_fp16(float* d, const uint32_t* a,
                                         const uint32_t* b) {
    asm volatile(
        "mma.sync.aligned.m16n8k16.row.col.f32.f16.f16.f32 "
        "{%0,%1,%2,%3},{%4,%5,%6,%7},{%8,%9},{%0,%1,%2,%3};"
        : "+f"(d[0]), "+f"(d[1]), "+f"(d[2]), "+f"(d[3])
        : "r"(a[0]), "r"(a[1]), "r"(a[2]), "r"(a[3]), "r"(b[0]), "r"(b[1]));
}

// one-time: weight[o][c][ky][kx] f32 -> swizzled fp16, layout
// [tap][o-row(128B)][cin], 16B-chunk swizzle: chunk ^= (o&7).
__global__ void wconv_kernel(const float* __restrict__ w) {
    int i = blockIdx.x * blockDim.x + threadIdx.x;
    if (i >= 64 * 64 * 9) return;
    int o = i / 576, r = i - o * 576, c = r / 9, k = r - c * 9;
    uint32_t off16 = k * 4096 + o * 64 + ((((c >> 3) ^ (o & 7)) << 3)) + (c & 7);
    g_w[off16] = __half_as_ushort(__float2half_rn(w[i]));
}

__global__ __launch_bounds__(TPB, 1)
void sbnet_mma_kernel(const float* __restrict__ x,
                      const float* __restrict__ mask,
                      const float* __restrict__ bias,
                      float* __restrict__ out) {
    extern __shared__ char smem[];
    const uint32_t sbase = smem_u32(smem);

    const int b   = blockIdx.x;
    const int n   = b >> 10;
    const int rem = b & (NBLK - 1);
    const int by  = rem >> 5, bx = rem & 31;
    const int t   = threadIdx.x;
    const int wid = t >> 5, lane = t & 31;
    const int y0  = by * BS, x0 = bx * BS;

    // ---- activity: threads 0..255 check the 16x16 gather window ----
    float mv = 0.f;
    if (t < 256) {
        int ty = t >> 4, tx = t & 15;
        int gy = y0 - 1 + ty, gx = x0 - 1 + tx;
        if ((unsigned)gy < (unsigned)Himg && (unsigned)gx < (unsigned)Wimg)
            mv = mask[(size_t)n * Himg * Wimg + gy * Wimg + gx];
    }
    const int act = __syncthreads_or(mv > 0.5f);

    if (!act) {  // zero-fill the 14x14 block for all 64 couts
        for (int i = t; i < 64 * 14 * 7; i += TPB) {
            int co = i / 98, r2 = i - co * 98, y = r2 / 7, j = r2 - y * 7;
            float2* op = (float2*)(out + (((size_t)n * 64 + co) * Himg + y0 + y) * Wimg
                                   + x0 + 2 * j);
            *op = make_float2(0.f, 0.f);
        }
        return;
    }

    // ---- staging: t<512 stage X (32 channels each); t>=512 copy W ----
    if (t < 512) {
        if (t < 64) *(float*)(smem + t * 4) = bias[t];
        const int p = t & 255, cb = (t >> 8) * 32;
        const int ty = p >> 4, tx = p & 15;
        const int gy = y0 - 1 + ty, gx = x0 - 1 + tx;
        const bool inb = (unsigned)gy < (unsigned)Himg && (unsigned)gx < (unsigned)Wimg;
        const float* xp = x + ((size_t)n * 64 + cb) * Himg * Wimg
                          + (size_t)gy * Wimg + gx;
        const int prow = p * 128, p7 = p & 7;
        #pragma unroll 4
        for (int ci = 0; ci < 32; ci++) {
            const int c = cb + ci;
            float v = inb ? xp[(size_t)ci * Himg * Wimg] : 0.f;
            __half hi = __float2half_rn(v);
            __half lo = __float2half_rn(v - __half2float(hi));
            uint32_t off = prow + ((((c >> 3) ^ p7) << 4)) + ((c & 7) << 1);
            *(uint16_t*)(smem + SM_X_HI + off) = __half_as_ushort(hi);
            *(uint16_t*)(smem + SM_X_LO + off) = __half_as_ushort(lo);
        }
    } else {
        const uint4* sw = (const uint4*)g_w;
        uint4* dw = (uint4*)(smem + SM_W);
        for (int i = t - 512; i < WB / 16; i += 384) dw[i] = sw[i];
    }
    __syncthreads();

    // ---- compute: warp = (mw 0..13) x (nhalf 0..1); tile M=16, N=32 ----
    const int nhalf = wid / 14;
    const int mw    = wid - nhalf * 14;    // output y-row = mw
    const int m0 = mw * 16;                // pixel rows [m0, m0+16) : y=mw
    const int n0 = nhalf * 32;             // cout block
    const int q  = lane >> 2, tq = lane & 3;

    float acc[4][4];
    #pragma unroll
    for (int nt = 0; nt < 4; nt++)
        #pragma unroll
        for (int i = 0; i < 4; i++) acc[nt][i] = 0.f;

    // per-lane invariants
    const int arow_l = (lane & 15);        // A: row within m16 tile
    const int ahi    = lane >> 4;          // A: k 16B-chunk select
    const int nrow   = n0 + (lane & 7) + ((lane & 16) >> 1);  // B row (cout)
    const int bhi    = (lane >> 3) & 1;    // B: k 16B-chunk select
    const uint32_t brow = sbase + nrow * 128;  // (nrow+16)&7 == nrow&7
    const int nx7 = nrow & 7;

    #pragma unroll 1
    for (int tap = 0; tap < 9; tap++) {
        const int ky = tap / 3;
        const int shift = ky * 16 + (tap - ky * 3);
        const int rowA = m0 + arow_l + shift;
        const uint32_t abase = sbase + (uint32_t)SM_X_HI + rowA * 128;
        const int a7 = rowA & 7;
        const uint32_t wt = (uint32_t)SM_W + tap * 8192;
        #pragma unroll
        for (int kc = 0; kc < 4; kc++) {
            uint32_t ah[4], al[4], bh[8];
            const uint32_t ch = (((kc * 2 + ahi) ^ a7) << 4);
            ldsm4(ah, abase + ch);
            ldsm4(al, abase + XB + ch);
            const uint32_t cb = (((kc * 2 + bhi) ^ nx7) << 4);
            const uint32_t bha = brow + wt + cb;
            ldsm4(bh + 0, bha);
            ldsm4(bh + 4, bha + 2048);
            // product-major: 4 independent MMAs between same-acc reuses
            #pragma unroll
            for (int nt = 0; nt < 4; nt++) mma_fp16(acc[nt], ah, bh + nt * 2);
            #pragma unroll
            for (int nt = 0; nt < 4; nt++) mma_fp16(acc[nt], al, bh + nt * 2);
        }
    }

    // ---- epilogue: bias + masked stores (y = mw < 14 by construction) ----
    const float* bias_s = (const float*)smem;
    {
        const int y = mw;
        #pragma unroll
        for (int nt = 0; nt < 4; nt++) {
            const int nb = n0 + nt * 8 + 2 * tq;
            const float b0 = bias_s[nb], b1 = bias_s[nb + 1];
            float* base = out + ((size_t)(n * 64 + nb) * Himg + (y0 + y)) * Wimg + x0;
            base[q] = acc[nt][0] + b0;
            base[(size_t)Himg * Wimg + q] = acc[nt][1] + b1;
            if (q < 6) {
                base[q + 8] = acc[nt][2] + b0;
                base[(size_t)Himg * Wimg + q + 8] = acc[nt][3] + b1;
            }
        }
    }
}

extern "C" void kernel_launch(void* const* d_in, const int* in_sizes, int n_in,
                              void* d_out, int out_size) {
    const float* x      = (const float*)d_in[0];
    const float* mask   = (const float*)d_in[1];
    const float* weight = (const float*)d_in[2];
    const float* bias   = (const float*)d_in[3];
    float* out = (float*)d_out;

    wconv_kernel<<<(64 * 64 * 9 + 255) / 256, 256>>>(weight);

    cudaFuncSetAttribute(sbnet_mma_kernel,
                         cudaFuncAttributeMaxDynamicSharedMemorySize, SMEM_TOTAL);
    sbnet_mma_kernel<<<4 * NBLK, TPB, SMEM_TOTAL>>>(x, mask, bias, out);
}